// round 2
// baseline (speedup 1.0000x reference)
#include <cuda_runtime.h>
#include <cstdint>
#include <cstddef>

// Problem constants
#define NPTS   131072
#define DIM    32
#define NLAY   4
#define NE     256
#define TILE_P 128
#define NTHREADS 512
#define NTILES (NPTS / TILE_P)      // 1024
#define GRID_MAIN 148

// smem strides chosen for bank-conflict-free access
#define CBS 260                      // cbT row stride in floats (rows stay 16B-aligned, LDS.128 conflict-free)
#define RS  129                      // res2 row stride in float2

#define ND_OUT   (NPTS * DIM)                 // 4194304
#define IDX_BASE (ND_OUT + 1)
#define OUT_FULL (ND_OUT + 1 + NPTS * NLAY)   // 4718593

// smem bytes: cbT 4*32*260*4 + cn 4*256*4 + res2 32*129*8 = 133120+4096+33024 = 170240
#define SMEM_BYTES 170240

__device__ float g_partials[GRID_MAIN];

// monotone float->uint key: ascending float => ascending uint (handles negatives)
__device__ __forceinline__ unsigned fkey(float x) {
    unsigned b = __float_as_uint(x);
    return (b & 0x80000000u) ? ~b : (b | 0x80000000u);
}

// packed dual fp32 FMA (Blackwell FFMA2 path, PTX-only)
__device__ __forceinline__ void fma2(unsigned long long& acc,
                                     unsigned long long a,
                                     unsigned long long b) {
    asm("fma.rn.f32x2 %0, %1, %2, %0;" : "+l"(acc) : "l"(a), "l"(b));
}

extern "C" __global__ void __launch_bounds__(NTHREADS, 1)
rvq_main(const float* __restrict__ x, const float* __restrict__ cb,
         float* __restrict__ out, int out_size)
{
    extern __shared__ float smem[];
    float*  cbT  = smem;                               // [NLAY][DIM][CBS]
    float*  cn   = cbT + NLAY * DIM * CBS;             // [NLAY][NE] codeword sq-norms
    float2* res2 = (float2*)(cn + NLAY * NE);          // [DIM][RS] residuals duplicated {r,r}
    __shared__ float s_warpsum[16];

    const int tid  = threadIdx.x;
    const int wid  = tid >> 5;
    const int lane = tid & 31;
    const int p0   = wid * 8;      // this warp's 8 points within the tile

    // ---- load codebooks into smem, transposed to [l][k][e] ----
    {
        const float4* cb4 = (const float4*)cb;    // 8192 float4s total
        #pragma unroll
        for (int i = 0; i < 16; i++) {
            int g = tid + i * NTHREADS;
            float4 v = cb4[g];
            int l   = g >> 11;            // 2048 float4 per layer
            int rem = g & 2047;
            int e   = rem >> 3;           // codeword index
            int k0  = (rem & 7) << 2;     // starting dim
            float* dst = cbT + (size_t)(l * DIM + k0) * CBS + e;
            dst[0]       = v.x;
            dst[CBS]     = v.y;
            dst[2 * CBS] = v.z;
            dst[3 * CBS] = v.w;
        }
    }
    __syncthreads();
    // ---- codeword squared norms ----
    for (int e2 = tid; e2 < NLAY * NE; e2 += NTHREADS) {
        int l = e2 >> 8, e = e2 & 255;
        const float* col = cbT + (size_t)l * DIM * CBS + e;
        float s = 0.f;
        #pragma unroll
        for (int k = 0; k < DIM; k++) { float c = col[k * CBS]; s = fmaf(c, c, s); }
        cn[e2] = s;
    }
    __syncthreads();

    float lane_loss = 0.f;

    for (int tile = blockIdx.x; tile < NTILES; tile += GRID_MAIN) {
        // ---- load x tile into res2 (each value duplicated into both f32x2 halves) ----
        {
            int p  = tid >> 2;               // 0..127 (warp w covers p0..p0+7)
            int k0 = (tid & 3) << 3;
            const float4* xg = (const float4*)(x + (size_t)(tile * TILE_P + p) * DIM + k0);
            float4 v0 = xg[0], v1 = xg[1];
            float vv[8] = {v0.x, v0.y, v0.z, v0.w, v1.x, v1.y, v1.z, v1.w};
            #pragma unroll
            for (int j = 0; j < 8; j++)
                res2[(k0 + j) * RS + p] = make_float2(vv[j], vv[j]);
        }
        __syncwarp();

        float my_idx_out = 0.f;

        for (int l = 0; l < NLAY; l++) {
            // acc[p][jj] : f32x2 dot accumulators, each holds a (lo,hi) code pair
            unsigned long long acc[8][4];
            #pragma unroll
            for (int p = 0; p < 8; p++)
                #pragma unroll
                for (int j = 0; j < 4; j++) acc[p][j] = 0ull;

            const float* cbl = cbT + (size_t)l * DIM * CBS + 4 * lane;
            #pragma unroll 4
            for (int k = 0; k < DIM; k++) {
                ulonglong2 b01 = *(const ulonglong2*)(cbl + (size_t)k * CBS);         // codes 4*lane..+3
                ulonglong2 b23 = *(const ulonglong2*)(cbl + (size_t)k * CBS + 128);   // codes 128+4*lane..+3
                const float2* rrow = res2 + k * RS + p0;
                #pragma unroll
                for (int p = 0; p < 8; p++) {
                    unsigned long long a = *(const unsigned long long*)(rrow + p); // {r,r} broadcast
                    fma2(acc[p][0], a, b01.x);
                    fma2(acc[p][1], a, b01.y);
                    fma2(acc[p][2], a, b23.x);
                    fma2(acc[p][3], a, b23.y);
                }
            }

            // ---- argmin epilogue ----
            float4 cnA = *(const float4*)(cn + l * NE + 4 * lane);
            float4 cnB = *(const float4*)(cn + l * NE + 128 + 4 * lane);
            float cna[8] = {cnA.x, cnA.y, cnA.z, cnA.w, cnB.x, cnB.y, cnB.z, cnB.w};

            #pragma unroll
            for (int p = 0; p < 8; p++) {
                float t[8];
                #pragma unroll
                for (int j = 0; j < 4; j++) {
                    double dd = __longlong_as_double((long long)acc[p][j]);
                    float lo = __int_as_float(__double2loint(dd));
                    float hi = __int_as_float(__double2hiint(dd));
                    t[2 * j]     = fmaf(-2.0f, lo, cna[2 * j]);       // ||c||^2 - 2 r.c  (||r||^2 const per row)
                    t[2 * j + 1] = fmaf(-2.0f, hi, cna[2 * j + 1]);
                }
                float best = fminf(fminf(fminf(t[0], t[1]), fminf(t[2], t[3])),
                                   fminf(fminf(t[4], t[5]), fminf(t[6], t[7])));
                unsigned wk = __reduce_min_sync(0xffffffffu, fkey(best));
                // first-occurrence (lowest index) tiebreak, matching jnp.argmin
                unsigned myc = 0xffffffffu;
                #pragma unroll
                for (int j = 7; j >= 0; j--) {
                    int code = (j < 4) ? (4 * lane + j) : (124 + 4 * lane + j);
                    if (fkey(t[j]) == wk) myc = (unsigned)code;
                }
                unsigned widx = __reduce_min_sync(0xffffffffu, myc);

                if (lane == 4 * p + l) my_idx_out = (float)widx;   // stash for coalesced idx write

                // ---- residual update (lane = dim k); codeword row from global (L2/L1-hot, 128KB total) ----
                float c = __ldg(cb + (size_t)(l * NE + (int)widx) * DIM + lane);
                int ri = lane * RS + p0 + p;
                float rv = res2[ri].x;
                float tt = rv - c;
                res2[ri] = make_float2(tt, tt);
                lane_loss = fmaf(tt, tt, lane_loss);   // (xq - r)^2 == residual_next^2
            }
            __syncwarp();
        } // layers

        // ---- write x_q = x - residual_final ----
        if (out_size >= ND_OUT) {
            int p  = tid >> 2;
            int k0 = (tid & 3) << 3;
            size_t base = (size_t)(tile * TILE_P + p) * DIM + k0;
            const float4* xg = (const float4*)(x + base);
            float4 v0 = xg[0], v1 = xg[1];
            float vv[8] = {v0.x, v0.y, v0.z, v0.w, v1.x, v1.y, v1.z, v1.w};
            float o[8];
            #pragma unroll
            for (int j = 0; j < 8; j++)
                o[j] = vv[j] - res2[(k0 + j) * RS + p].x;
            float4* og = (float4*)(out + base);
            og[0] = make_float4(o[0], o[1], o[2], o[3]);
            og[1] = make_float4(o[4], o[5], o[6], o[7]);
        }
        // ---- write indices (as float), coalesced: 32 consecutive = 8 points x 4 layers ----
        if (out_size >= OUT_FULL) {
            out[(size_t)IDX_BASE + (size_t)(tile * TILE_P + p0) * NLAY + lane] = my_idx_out;
        }
        __syncwarp();
    } // tiles

    // ---- deterministic per-CTA loss partial ----
    float v = lane_loss;
    #pragma unroll
    for (int o = 16; o; o >>= 1) v += __shfl_xor_sync(0xffffffffu, v, o);
    if (lane == 0) s_warpsum[wid] = v;
    __syncthreads();
    if (tid == 0) {
        float s = 0.f;
        #pragma unroll
        for (int w = 0; w < 16; w++) s += s_warpsum[w];
        g_partials[blockIdx.x] = s;
    }
}

extern "C" __global__ void rvq_loss_reduce(float* __restrict__ out, int out_size) {
    __shared__ float buf[256];
    int t = threadIdx.x;
    buf[t] = (t < GRID_MAIN) ? g_partials[t] : 0.f;
    __syncthreads();
    #pragma unroll
    for (int s = 128; s; s >>= 1) {
        if (t < s) buf[t] += buf[t + s];
        __syncthreads();
    }
    // mean_loss = (1+beta)/(L*N*D) * total
    if (t == 0 && out_size > ND_OUT)
        out[ND_OUT] = buf[0] * (1.25f / (float)((size_t)NLAY * NPTS * DIM));
}

extern "C" void kernel_launch(void* const* d_in, const int* in_sizes, int n_in,
                              void* d_out, int out_size)
{
    const float* x  = (const float*)d_in[0];
    const float* cb = (const float*)d_in[1];
    float* out = (float*)d_out;

    static bool attr_set = false;
    if (!attr_set) {
        cudaFuncSetAttribute(rvq_main, cudaFuncAttributeMaxDynamicSharedMemorySize, SMEM_BYTES);
        attr_set = true;
    }

    rvq_main<<<GRID_MAIN, NTHREADS, SMEM_BYTES>>>(x, cb, out, out_size);
    rvq_loss_reduce<<<1, 256>>>(out, out_size);
}

// round 11
// speedup vs baseline: 1.0160x; 1.0160x over previous
#include <cuda_runtime.h>
#include <cstdint>
#include <cstddef>

// Problem constants
#define NPTS   131072
#define DIM    32
#define NLAY   4
#define NE     256
#define TILE_P 128
#define NTHREADS 512
#define NTILES (NPTS / TILE_P)      // 1024
#define GRID_MAIN 148

// smem strides chosen for alignment / conflict behavior
#define CBS 260   // cbT row stride in floats: rows 16B-aligned -> conflict-free LDS.128 of code fragments
#define RS  130   // res2 row stride in float2 (EVEN -> every (k, even p) is 16B aligned for LDS.128 broadcast)

#define ND_OUT   (NPTS * DIM)                 // 4194304
#define IDX_BASE (ND_OUT + 1)
#define OUT_FULL (ND_OUT + 1 + NPTS * NLAY)   // 4718593

// smem bytes: cbT 4*32*260*4 = 133120, cn 4*256*4 = 4096, res2 32*130*8 = 33280  -> 170496
#define SMEM_BYTES 170496

__device__ float g_partials[GRID_MAIN];

// monotone float->uint key: ascending float => ascending uint (handles negatives)
__device__ __forceinline__ unsigned fkey(float x) {
    unsigned b = __float_as_uint(x);
    return (b & 0x80000000u) ? ~b : (b | 0x80000000u);
}

// packed dual fp32 FMA (Blackwell FFMA2 path, PTX-only)
__device__ __forceinline__ void fma2(unsigned long long& acc,
                                     unsigned long long a,
                                     unsigned long long b) {
    asm("fma.rn.f32x2 %0, %1, %2, %0;" : "+l"(acc) : "l"(a), "l"(b));
}

extern "C" __global__ void __launch_bounds__(NTHREADS, 1)
rvq_main(const float* __restrict__ x, const float* __restrict__ cb,
         float* __restrict__ out, int out_size)
{
    extern __shared__ float smem[];
    float*  cbT  = smem;                               // [NLAY][DIM][CBS], transposed [l][k][e]
    float*  cn   = cbT + NLAY * DIM * CBS;             // [NLAY][NE] codeword sq-norms
    float2* res2 = (float2*)(cn + NLAY * NE);          // [DIM][RS] residuals duplicated {r,r}
    __shared__ float s_warpsum[16];

    const int tid  = threadIdx.x;
    const int wid  = tid >> 5;
    const int lane = tid & 31;
    const int p0   = wid * 8;      // this warp's 8 points within the tile

    // ---- load codebooks into smem, transposed to [l][k][e] ----
    {
        const float4* cb4 = (const float4*)cb;    // 8192 float4s total
        #pragma unroll
        for (int i = 0; i < 16; i++) {
            int g = tid + i * NTHREADS;
            float4 v = cb4[g];
            int l   = g >> 11;            // 2048 float4 per layer
            int rem = g & 2047;
            int e   = rem >> 3;           // codeword index
            int k0  = (rem & 7) << 2;     // starting dim
            float* dst = cbT + (size_t)(l * DIM + k0) * CBS + e;
            dst[0]       = v.x;
            dst[CBS]     = v.y;
            dst[2 * CBS] = v.z;
            dst[3 * CBS] = v.w;
        }
    }
    __syncthreads();
    // ---- codeword squared norms ----
    for (int e2 = tid; e2 < NLAY * NE; e2 += NTHREADS) {
        int l = e2 >> 8, e = e2 & 255;
        const float* col = cbT + (size_t)l * DIM * CBS + e;
        float s = 0.f;
        #pragma unroll
        for (int k = 0; k < DIM; k++) { float c = col[k * CBS]; s = fmaf(c, c, s); }
        cn[e2] = s;
    }
    __syncthreads();

    float lane_loss = 0.f;

    for (int tile = blockIdx.x; tile < NTILES; tile += GRID_MAIN) {
        // ---- load x tile into res2 (each value duplicated into both f32x2 halves) ----
        {
            int p  = tid >> 2;               // 0..127 (warp w covers p0..p0+7)
            int k0 = (tid & 3) << 3;
            const float4* xg = (const float4*)(x + (size_t)(tile * TILE_P + p) * DIM + k0);
            float4 v0 = xg[0], v1 = xg[1];
            float vv[8] = {v0.x, v0.y, v0.z, v0.w, v1.x, v1.y, v1.z, v1.w};
            #pragma unroll
            for (int j = 0; j < 8; j++)
                res2[(k0 + j) * RS + p] = make_float2(vv[j], vv[j]);
        }
        __syncwarp();

        float my_idx_out = 0.f;

        for (int l = 0; l < NLAY; l++) {
            // acc[p][jj] : f32x2 dot accumulators, each holds a (lo,hi) code pair
            unsigned long long acc[8][4];
            #pragma unroll
            for (int p = 0; p < 8; p++)
                #pragma unroll
                for (int j = 0; j < 4; j++) acc[p][j] = 0ull;

            const float* cbl = cbT + (size_t)l * DIM * CBS + 4 * lane;
            #pragma unroll 4
            for (int k = 0; k < DIM; k++) {
                // codes: 2x LDS.128, conflict-free (lanes cover 512B contiguous)
                ulonglong2 b01 = *(const ulonglong2*)(cbl + (size_t)k * CBS);         // codes 4*lane..+3
                ulonglong2 b23 = *(const ulonglong2*)(cbl + (size_t)k * CBS + 128);   // codes 128+4*lane..+3
                // residuals: 4x broadcast LDS.128, each carries two duplicated points
                const ulonglong2* rrow = (const ulonglong2*)(res2 + k * RS + p0);     // 16B aligned (RS even, p0 even)
                #pragma unroll
                for (int i = 0; i < 4; i++) {
                    ulonglong2 a2 = rrow[i];              // {r_{2i},r_{2i}, r_{2i+1},r_{2i+1}}
                    fma2(acc[2*i][0], a2.x, b01.x);
                    fma2(acc[2*i][1], a2.x, b01.y);
                    fma2(acc[2*i][2], a2.x, b23.x);
                    fma2(acc[2*i][3], a2.x, b23.y);
                    fma2(acc[2*i+1][0], a2.y, b01.x);
                    fma2(acc[2*i+1][1], a2.y, b01.y);
                    fma2(acc[2*i+1][2], a2.y, b23.x);
                    fma2(acc[2*i+1][3], a2.y, b23.y);
                }
            }

            // ---- argmin epilogue ----
            float4 cnA = *(const float4*)(cn + l * NE + 4 * lane);
            float4 cnB = *(const float4*)(cn + l * NE + 128 + 4 * lane);
            float cna[8] = {cnA.x, cnA.y, cnA.z, cnA.w, cnB.x, cnB.y, cnB.z, cnB.w};

            #pragma unroll
            for (int p = 0; p < 8; p++) {
                float t[8];
                #pragma unroll
                for (int j = 0; j < 4; j++) {
                    double dd = __longlong_as_double((long long)acc[p][j]);
                    float lo = __int_as_float(__double2loint(dd));
                    float hi = __int_as_float(__double2hiint(dd));
                    t[2 * j]     = fmaf(-2.0f, lo, cna[2 * j]);       // ||c||^2 - 2 r.c  (||r||^2 const per row)
                    t[2 * j + 1] = fmaf(-2.0f, hi, cna[2 * j + 1]);
                }
                float best = fminf(fminf(fminf(t[0], t[1]), fminf(t[2], t[3])),
                                   fminf(fminf(t[4], t[5]), fminf(t[6], t[7])));
                unsigned wk = __reduce_min_sync(0xffffffffu, fkey(best));
                // first-occurrence (lowest index) tiebreak, matching jnp.argmin
                unsigned myc = 0xffffffffu;
                #pragma unroll
                for (int j = 7; j >= 0; j--) {
                    int code = (j < 4) ? (4 * lane + j) : (124 + 4 * lane + j);
                    if (fkey(t[j]) == wk) myc = (unsigned)code;
                }
                unsigned widx = __reduce_min_sync(0xffffffffu, myc);

                if (lane == 4 * p + l) my_idx_out = (float)widx;   // stash for coalesced idx write

                // ---- residual update (lane = dim k); gather codeword from SMEM (no L2 round-trip) ----
                float c = cbT[(size_t)(l * DIM + lane) * CBS + (int)widx];
                int ri = lane * RS + p0 + p;
                float rv = res2[ri].x;
                float tt = rv - c;
                res2[ri] = make_float2(tt, tt);
                lane_loss = fmaf(tt, tt, lane_loss);   // (xq - r)^2 == residual_next^2
            }
            __syncwarp();
        } // layers

        // ---- write x_q = x - residual_final ----
        if (out_size >= ND_OUT) {
            int p  = tid >> 2;
            int k0 = (tid & 3) << 3;
            size_t base = (size_t)(tile * TILE_P + p) * DIM + k0;
            const float4* xg = (const float4*)(x + base);
            float4 v0 = xg[0], v1 = xg[1];
            float vv[8] = {v0.x, v0.y, v0.z, v0.w, v1.x, v1.y, v1.z, v1.w};
            float o[8];
            #pragma unroll
            for (int j = 0; j < 8; j++)
                o[j] = vv[j] - res2[(k0 + j) * RS + p].x;
            float4* og = (float4*)(out + base);
            og[0] = make_float4(o[0], o[1], o[2], o[3]);
            og[1] = make_float4(o[4], o[5], o[6], o[7]);
        }
        // ---- write indices (as float), coalesced: 32 consecutive = 8 points x 4 layers ----
        if (out_size >= OUT_FULL) {
            out[(size_t)IDX_BASE + (size_t)(tile * TILE_P + p0) * NLAY + lane] = my_idx_out;
        }
        __syncwarp();
    } // tiles

    // ---- deterministic per-CTA loss partial ----
    float v = lane_loss;
    #pragma unroll
    for (int o = 16; o; o >>= 1) v += __shfl_xor_sync(0xffffffffu, v, o);
    if (lane == 0) s_warpsum[wid] = v;
    __syncthreads();
    if (tid == 0) {
        float s = 0.f;
        #pragma unroll
        for (int w = 0; w < 16; w++) s += s_warpsum[w];
        g_partials[blockIdx.x] = s;
    }
}

extern "C" __global__ void rvq_loss_reduce(float* __restrict__ out, int out_size) {
    __shared__ float buf[256];
    int t = threadIdx.x;
    buf[t] = (t < GRID_MAIN) ? g_partials[t] : 0.f;
    __syncthreads();
    #pragma unroll
    for (int s = 128; s; s >>= 1) {
        if (t < s) buf[t] += buf[t + s];
        __syncthreads();
    }
    // mean_loss = (1+beta)/(L*N*D) * total
    if (t == 0 && out_size > ND_OUT)
        out[ND_OUT] = buf[0] * (1.25f / (float)((size_t)NLAY * NPTS * DIM));
}

extern "C" void kernel_launch(void* const* d_in, const int* in_sizes, int n_in,
                              void* d_out, int out_size)
{
    const float* x  = (const float*)d_in[0];
    const float* cb = (const float*)d_in[1];
    float* out = (float*)d_out;

    cudaFuncSetAttribute(rvq_main, cudaFuncAttributeMaxDynamicSharedMemorySize, SMEM_BYTES);

    rvq_main<<<GRID_MAIN, NTHREADS, SMEM_BYTES>>>(x, cb, out, out_size);
    rvq_loss_reduce<<<1, 256>>>(out, out_size);
}

// round 14
// speedup vs baseline: 1.0166x; 1.0006x over previous
#include <cuda_runtime.h>
#include <cstdint>
#include <cstddef>

// Problem constants
#define NPTS   131072
#define DIM    32
#define NLAY   4
#define NE     256
#define TILE_P 128
#define NTHREADS 512
#define NTILES (NPTS / TILE_P)      // 1024
#define GRID_MAIN 148

// smem strides chosen for alignment / conflict behavior
#define CBS 260   // cbT row stride in floats: rows 16B-aligned -> conflict-free LDS.128 of code fragments
#define RS  130   // res2 row stride in float2 (EVEN -> every (k, even p) is 16B aligned for LDS.128 broadcast)

#define ND_OUT   (NPTS * DIM)                 // 4194304
#define IDX_BASE (ND_OUT + 1)
#define OUT_FULL (ND_OUT + 1 + NPTS * NLAY)   // 4718593

// smem bytes: cbT 4*32*260*4 = 133120, cn 4*256*4 = 4096, res2 32*130*8 = 33280  -> 170496
#define SMEM_BYTES 170496

__device__ float g_partials[GRID_MAIN];
__device__ unsigned int g_done = 0;

// monotone float->uint key: ascending float => ascending uint (handles negatives)
__device__ __forceinline__ unsigned fkey(float x) {
    unsigned b = __float_as_uint(x);
    return (b & 0x80000000u) ? ~b : (b | 0x80000000u);
}

// packed dual fp32 FMA (Blackwell FFMA2 path, PTX-only)
__device__ __forceinline__ void fma2(unsigned long long& acc,
                                     unsigned long long a,
                                     unsigned long long b) {
    asm("fma.rn.f32x2 %0, %1, %2, %0;" : "+l"(acc) : "l"(a), "l"(b));
}

extern "C" __global__ void __launch_bounds__(NTHREADS, 1)
rvq_main(const float* __restrict__ x, const float* __restrict__ cb,
         float* __restrict__ out, int out_size)
{
    extern __shared__ float smem[];
    float*  cbT  = smem;                               // [NLAY][DIM][CBS], transposed [l][k][e]
    float*  cn   = cbT + NLAY * DIM * CBS;             // [NLAY][NE] codeword sq-norms
    float2* res2 = (float2*)(cn + NLAY * NE);          // [DIM][RS] residuals duplicated {r,r}
    __shared__ float s_warpsum[16];
    __shared__ bool  s_isLast;

    const int tid  = threadIdx.x;
    const int wid  = tid >> 5;
    const int lane = tid & 31;
    const int p0   = wid * 8;      // this warp's 8 points within the tile

    // ---- load codebooks into smem, transposed to [l][k][e] ----
    {
        const float4* cb4 = (const float4*)cb;    // 8192 float4s total
        #pragma unroll
        for (int i = 0; i < 16; i++) {
            int g = tid + i * NTHREADS;
            float4 v = cb4[g];
            int l   = g >> 11;            // 2048 float4 per layer
            int rem = g & 2047;
            int e   = rem >> 3;           // codeword index
            int k0  = (rem & 7) << 2;     // starting dim
            float* dst = cbT + (size_t)(l * DIM + k0) * CBS + e;
            dst[0]       = v.x;
            dst[CBS]     = v.y;
            dst[2 * CBS] = v.z;
            dst[3 * CBS] = v.w;
        }
    }
    __syncthreads();
    // ---- codeword squared norms ----
    for (int e2 = tid; e2 < NLAY * NE; e2 += NTHREADS) {
        int l = e2 >> 8, e = e2 & 255;
        const float* col = cbT + (size_t)l * DIM * CBS + e;
        float s = 0.f;
        #pragma unroll
        for (int k = 0; k < DIM; k++) { float c = col[k * CBS]; s = fmaf(c, c, s); }
        cn[e2] = s;
    }
    __syncthreads();

    float lane_loss = 0.f;

    for (int tile = blockIdx.x; tile < NTILES; tile += GRID_MAIN) {
        // ---- load x tile into res2 (each value duplicated into both f32x2 halves) ----
        {
            int p  = tid >> 2;               // 0..127 (warp w covers p0..p0+7)
            int k0 = (tid & 3) << 3;
            const float4* xg = (const float4*)(x + (size_t)(tile * TILE_P + p) * DIM + k0);
            float4 v0 = xg[0], v1 = xg[1];
            float vv[8] = {v0.x, v0.y, v0.z, v0.w, v1.x, v1.y, v1.z, v1.w};
            #pragma unroll
            for (int j = 0; j < 8; j++)
                res2[(k0 + j) * RS + p] = make_float2(vv[j], vv[j]);
        }
        __syncwarp();

        float my_idx_out = 0.f;

        for (int l = 0; l < NLAY; l++) {
            // acc[p][jj] : f32x2 dot accumulators, each holds a (lo,hi) code pair
            unsigned long long acc[8][4];
            #pragma unroll
            for (int p = 0; p < 8; p++)
                #pragma unroll
                for (int j = 0; j < 4; j++) acc[p][j] = 0ull;

            const float* cbl = cbT + (size_t)l * DIM * CBS + 4 * lane;
            #pragma unroll 4
            for (int k = 0; k < DIM; k++) {
                // codes: 2x LDS.128, conflict-free (lanes cover 512B contiguous)
                ulonglong2 b01 = *(const ulonglong2*)(cbl + (size_t)k * CBS);         // codes 4*lane..+3
                ulonglong2 b23 = *(const ulonglong2*)(cbl + (size_t)k * CBS + 128);   // codes 128+4*lane..+3
                // residuals: 4x broadcast LDS.128, each carries two duplicated points
                const ulonglong2* rrow = (const ulonglong2*)(res2 + k * RS + p0);     // 16B aligned (RS even, p0 even)
                #pragma unroll
                for (int i = 0; i < 4; i++) {
                    ulonglong2 a2 = rrow[i];              // {r_{2i},r_{2i}, r_{2i+1},r_{2i+1}}
                    fma2(acc[2*i][0], a2.x, b01.x);
                    fma2(acc[2*i][1], a2.x, b01.y);
                    fma2(acc[2*i][2], a2.x, b23.x);
                    fma2(acc[2*i][3], a2.x, b23.y);
                    fma2(acc[2*i+1][0], a2.y, b01.x);
                    fma2(acc[2*i+1][1], a2.y, b01.y);
                    fma2(acc[2*i+1][2], a2.y, b23.x);
                    fma2(acc[2*i+1][3], a2.y, b23.y);
                }
            }

            // ---- argmin epilogue ----
            float4 cnA = *(const float4*)(cn + l * NE + 4 * lane);
            float4 cnB = *(const float4*)(cn + l * NE + 128 + 4 * lane);
            float cna[8] = {cnA.x, cnA.y, cnA.z, cnA.w, cnB.x, cnB.y, cnB.z, cnB.w};

            #pragma unroll
            for (int p = 0; p < 8; p++) {
                float t[8];
                #pragma unroll
                for (int j = 0; j < 4; j++) {
                    double dd = __longlong_as_double((long long)acc[p][j]);
                    float lo = __int_as_float(__double2loint(dd));
                    float hi = __int_as_float(__double2hiint(dd));
                    t[2 * j]     = fmaf(-2.0f, lo, cna[2 * j]);       // ||c||^2 - 2 r.c  (||r||^2 const per row)
                    t[2 * j + 1] = fmaf(-2.0f, hi, cna[2 * j + 1]);
                }
                float best = fminf(fminf(fminf(t[0], t[1]), fminf(t[2], t[3])),
                                   fminf(fminf(t[4], t[5]), fminf(t[6], t[7])));
                unsigned wk = __reduce_min_sync(0xffffffffu, fkey(best));
                // first-occurrence (lowest index) tiebreak, matching jnp.argmin
                unsigned myc = 0xffffffffu;
                #pragma unroll
                for (int j = 7; j >= 0; j--) {
                    int code = (j < 4) ? (4 * lane + j) : (124 + 4 * lane + j);
                    if (fkey(t[j]) == wk) myc = (unsigned)code;
                }
                unsigned widx = __reduce_min_sync(0xffffffffu, myc);

                if (lane == 4 * p + l) my_idx_out = (float)widx;   // stash for coalesced idx write

                // ---- residual update (lane = dim k); gather codeword from SMEM (no L2 round-trip) ----
                float c = cbT[(size_t)(l * DIM + lane) * CBS + (int)widx];
                int ri = lane * RS + p0 + p;
                float rv = res2[ri].x;
                float tt = rv - c;
                res2[ri] = make_float2(tt, tt);
                lane_loss = fmaf(tt, tt, lane_loss);   // (xq - r)^2 == residual_next^2
            }
            __syncwarp();
        } // layers

        // ---- write x_q = x - residual_final ----
        if (out_size >= ND_OUT) {
            int p  = tid >> 2;
            int k0 = (tid & 3) << 3;
            size_t base = (size_t)(tile * TILE_P + p) * DIM + k0;
            const float4* xg = (const float4*)(x + base);
            float4 v0 = xg[0], v1 = xg[1];
            float vv[8] = {v0.x, v0.y, v0.z, v0.w, v1.x, v1.y, v1.z, v1.w};
            float o[8];
            #pragma unroll
            for (int j = 0; j < 8; j++)
                o[j] = vv[j] - res2[(k0 + j) * RS + p].x;
            float4* og = (float4*)(out + base);
            og[0] = make_float4(o[0], o[1], o[2], o[3]);
            og[1] = make_float4(o[4], o[5], o[6], o[7]);
        }
        // ---- write indices (as float), coalesced: 32 consecutive = 8 points x 4 layers ----
        if (out_size >= OUT_FULL) {
            out[(size_t)IDX_BASE + (size_t)(tile * TILE_P + p0) * NLAY + lane] = my_idx_out;
        }
        __syncwarp();
    } // tiles

    // ---- deterministic per-CTA loss partial ----
    float v = lane_loss;
    #pragma unroll
    for (int o = 16; o; o >>= 1) v += __shfl_xor_sync(0xffffffffu, v, o);
    if (lane == 0) s_warpsum[wid] = v;
    __syncthreads();
    if (tid == 0) {
        float s = 0.f;
        #pragma unroll
        for (int w = 0; w < 16; w++) s += s_warpsum[w];
        g_partials[blockIdx.x] = s;
        __threadfence();
        unsigned old = atomicAdd(&g_done, 1u);
        s_isLast = (old == GRID_MAIN - 1);
    }
    __syncthreads();

    // ---- last CTA reduces all partials and writes the loss (deterministic order) ----
    if (s_isLast && wid == 0) {
        __threadfence();   // make all g_partials writes visible
        float s = 0.f;
        #pragma unroll
        for (int i = 0; i < 5; i++) {
            int idx = lane + i * 32;
            if (idx < GRID_MAIN) s += g_partials[idx];
        }
        #pragma unroll
        for (int o = 16; o; o >>= 1) s += __shfl_xor_sync(0xffffffffu, s, o);
        if (lane == 0) {
            if (out_size > ND_OUT)
                out[ND_OUT] = s * (1.25f / (float)((size_t)NLAY * NPTS * DIM));
            g_done = 0;            // reset ticket for next call / graph replay
            __threadfence();
        }
    }
}

extern "C" void kernel_launch(void* const* d_in, const int* in_sizes, int n_in,
                              void* d_out, int out_size)
{
    const float* x  = (const float*)d_in[0];
    const float* cb = (const float*)d_in[1];
    float* out = (float*)d_out;

    cudaFuncSetAttribute(rvq_main, cudaFuncAttributeMaxDynamicSharedMemorySize, SMEM_BYTES);

    rvq_main<<<GRID_MAIN, NTHREADS, SMEM_BYTES>>>(x, cb, out, out_size);
}